// round 3
// baseline (speedup 1.0000x reference)
#include <cuda_runtime.h>
#include <cstdint>

// Problem constants
#define BS   64
#define IC   256     // in_dim (GEMM K)
#define NPIX 256     // 16*16 pixels (I = num_in_caps)
#define J    64      // out caps
#define D2   32      // out_dim per cap
#define OUT  2048    // J*D2

// pred layout: [b][j][i][d]  (b: batch, j: out-cap, i: pixel/in-cap, d: dim)
__device__ float g_pred[(size_t)BS * J * NPIX * D2];   // 134 MB scratch

// ---------------------------------------------------------------------------
// Kernel 1: batched SGEMM  pred[b][j][i][d] = sum_ic W[(j*32+d)*256+ic]*x[b][ic][i] + Wb
// Tile 64(o) x 64(i), BK=16, 256 threads, 4x4 microtile.
// ---------------------------------------------------------------------------
#define BM 64
#define BN 64
#define BK 16

__global__ __launch_bounds__(256) void gemm_kernel(
    const float* __restrict__ W,
    const float* __restrict__ x,
    const float* __restrict__ Wb)
{
    __shared__ float As[BK][BM];      // A transposed: As[k][o_local]
    __shared__ float Bs[BK][BN];      // Bs[k][i_local]
    __shared__ float Cs[BM][BN + 1];  // padded staging for coalesced epilogue

    const int b  = blockIdx.z;
    const int o0 = blockIdx.x * BM;   // output-channel tile base
    const int i0 = blockIdx.y * BN;   // pixel tile base
    const int tid = threadIdx.x;
    const int ty = tid >> 4;          // 0..15
    const int tx = tid & 15;          // 0..15

    const float* xb = x + (size_t)b * IC * NPIX;

    float acc[4][4];
    #pragma unroll
    for (int r = 0; r < 4; r++)
        #pragma unroll
        for (int c = 0; c < 4; c++) acc[r][c] = 0.f;

    for (int k0 = 0; k0 < IC; k0 += BK) {
        // Load A tile: W[o0+r][k0+c4..c4+3] (float4, coalesced)
        {
            int r  = tid >> 2;            // 0..63
            int c4 = (tid & 3) * 4;       // 0,4,8,12
            float4 a = *reinterpret_cast<const float4*>(W + (size_t)(o0 + r) * IC + k0 + c4);
            As[c4 + 0][r] = a.x;
            As[c4 + 1][r] = a.y;
            As[c4 + 2][r] = a.z;
            As[c4 + 3][r] = a.w;
        }
        // Load B tile: x[b][k0+row][i0+col]
        {
            int col = tid & 63;
            int rb  = (tid >> 6) * 4;     // 0,4,8,12
            #pragma unroll
            for (int q = 0; q < 4; q++) {
                int row = rb + q;
                Bs[row][col] = xb[(size_t)(k0 + row) * NPIX + i0 + col];
            }
        }
        __syncthreads();

        #pragma unroll
        for (int k = 0; k < BK; k++) {
            float4 av = *reinterpret_cast<const float4*>(&As[k][ty * 4]);
            float4 bv = *reinterpret_cast<const float4*>(&Bs[k][tx * 4]);
            float ar[4] = {av.x, av.y, av.z, av.w};
            float br[4] = {bv.x, bv.y, bv.z, bv.w};
            #pragma unroll
            for (int r = 0; r < 4; r++)
                #pragma unroll
                for (int c = 0; c < 4; c++)
                    acc[r][c] = fmaf(ar[r], br[c], acc[r][c]);
        }
        __syncthreads();
    }

    // Stage to smem with bias
    #pragma unroll
    for (int r = 0; r < 4; r++) {
        float bias = Wb[o0 + ty * 4 + r];
        #pragma unroll
        for (int c = 0; c < 4; c++)
            Cs[ty * 4 + r][tx * 4 + c] = acc[r][c] + bias;
    }
    __syncthreads();

    // Coalesced write-out: pred[b][j0+jl][i0+il][d] <- Cs[jl*32+d][il]
    // 128 lines (jl in 0..1, il in 0..63), each 32 contiguous floats.
    const int j0 = o0 >> 5;
    for (int e = tid; e < BM * BN; e += 256) {
        int d    = e & 31;
        int line = e >> 5;        // 0..127
        int jl   = line >> 6;     // 0..1
        int il   = line & 63;     // 0..63
        size_t dst = ((((size_t)b * J + j0 + jl) * NPIX) + (i0 + il)) * D2 + d;
        g_pred[dst] = Cs[jl * 32 + d][il];
    }
}

// ---------------------------------------------------------------------------
// Kernel 2: fused dynamic routing (3 iterations), one CTA per batch sample.
// smem: logits L[64][256], per-i softmax stats, s[64][32], v[64][32].
// ---------------------------------------------------------------------------
__global__ __launch_bounds__(1024, 1) void routing_kernel(
    const float* __restrict__ b_init,
    float* __restrict__ out)
{
    extern __shared__ float smem[];
    float* L    = smem;                 // 64*256 = 16384
    float* mx   = L + J * NPIX;         // 256
    float* rden = mx + NPIX;            // 256
    float* sbuf = rden + NPIX;          // 64*32 = 2048
    float* vbuf = sbuf + J * D2;        // 64*32 = 2048

    const int b    = blockIdx.x;
    const int tid  = threadIdx.x;
    const int wid  = tid >> 5;          // 0..31
    const int lane = tid & 31;

    const float* P = g_pred + (size_t)b * J * NPIX * D2;

    // load logits
    for (int idx = tid; idx < J * NPIX; idx += 1024)
        L[idx] = b_init[(size_t)b * J * NPIX + idx];
    __syncthreads();

    for (int it = 0; it < 3; it++) {
        // ---- Phase A: per-i softmax stats over J (threads 0..255) ----
        if (tid < NPIX) {
            int i = tid;
            float m = -1e30f;
            #pragma unroll 4
            for (int j = 0; j < J; j++) m = fmaxf(m, L[j * NPIX + i]);
            float sum = 0.f;
            #pragma unroll 4
            for (int j = 0; j < J; j++) sum += __expf(L[j * NPIX + i] - m);
            mx[i]   = m;
            rden[i] = 1.0f / sum;
        }
        __syncthreads();

        // ---- Phase B: s[j][d] = sum_i c[j][i] * P[j][i][d] ----
        // warp w handles j = 2w, 2w+1; lane = d. Coalesced 128B panel reads.
        #pragma unroll
        for (int jj = 0; jj < 2; jj++) {
            int j = wid * 2 + jj;
            const float* Pj = P + (size_t)j * NPIX * D2;
            const float* Lj = L + j * NPIX;
            float acc = 0.f;
            #pragma unroll 4
            for (int i = 0; i < NPIX; i++) {
                float c = __expf(Lj[i] - mx[i]) * rden[i];
                acc = fmaf(c, Pj[i * D2 + lane], acc);
            }
            sbuf[j * D2 + lane] = acc;
        }
        __syncthreads();

        // ---- Phase C: squash ----
        #pragma unroll
        for (int jj = 0; jj < 2; jj++) {
            int j = wid * 2 + jj;
            float sv = sbuf[j * D2 + lane];
            float sq = sv * sv;
            #pragma unroll
            for (int o = 16; o; o >>= 1) sq += __shfl_xor_sync(0xFFFFFFFFu, sq, o);
            float val = (sq / (1.0f + sq)) * sv * rsqrtf(sq + 1e-8f);
            vbuf[j * D2 + lane] = val;
            if (it == 2) out[(size_t)b * OUT + j * D2 + lane] = val;
        }
        if (it == 2) break;
        __syncthreads();

        // ---- Phase D: L[j][i] += sum_d v[j][d] * P[j][i][d] ----
        // Lane owns i-rows; float4 dot of 128B panels (L1 absorbs transpose).
        #pragma unroll
        for (int jj = 0; jj < 2; jj++) {
            int j = wid * 2 + jj;
            const float* Pj = P + (size_t)j * NPIX * D2;
            const float4* v4 = reinterpret_cast<const float4*>(vbuf + j * D2);
            float4 vr[8];
            #pragma unroll
            for (int u = 0; u < 8; u++) vr[u] = v4[u];
            #pragma unroll
            for (int q = 0; q < 8; q++) {
                int i = q * 32 + lane;
                const float4* p4 = reinterpret_cast<const float4*>(Pj + (size_t)i * D2);
                float acc = 0.f;
                #pragma unroll
                for (int u = 0; u < 8; u++) {
                    float4 pv = p4[u];
                    acc += pv.x * vr[u].x + pv.y * vr[u].y
                         + pv.z * vr[u].z + pv.w * vr[u].w;
                }
                L[j * NPIX + i] += acc;
            }
        }
        __syncthreads();
    }
}

// ---------------------------------------------------------------------------
// Launch
// Inputs (metadata order): x[64,256,16,16] f32, b_init[64,64,256] f32,
//                          W[2048,256] f32, Wb[2048] f32
// Output: v[64,64,32] f32
// ---------------------------------------------------------------------------
extern "C" void kernel_launch(void* const* d_in, const int* in_sizes, int n_in,
                              void* d_out, int out_size)
{
    const float* x      = (const float*)d_in[0];
    const float* b_init = (const float*)d_in[1];
    const float* W      = (const float*)d_in[2];
    const float* Wb     = (const float*)d_in[3];
    float* out = (float*)d_out;

    // GEMM: grid (o-tiles=32, i-tiles=4, batch=64)
    dim3 ggrid(OUT / BM, NPIX / BN, BS);
    gemm_kernel<<<ggrid, 256>>>(W, x, Wb);

    // Routing: one CTA per batch, 84 KB dynamic smem
    const int smem_bytes = (J * NPIX + NPIX + NPIX + J * D2 + J * D2) * (int)sizeof(float);
    cudaFuncSetAttribute(routing_kernel,
                         cudaFuncAttributeMaxDynamicSharedMemorySize, smem_bytes);
    routing_kernel<<<BS, 1024, smem_bytes>>>(b_init, out);
}

// round 5
// speedup vs baseline: 1.4622x; 1.4622x over previous
#include <cuda_runtime.h>
#include <cstdint>

// Problem constants
#define BS   64
#define IC   256     // in_dim (GEMM K)
#define NPIX 256     // 16*16 pixels (I = num_in_caps)
#define J    64      // out caps
#define D2   32      // out_dim per cap
#define OUT  2048    // J*D2

#define NCH  16      // i-chunks for routing
#define CHI  (NPIX / NCH)   // 16 pixels per chunk

// pred layout: [b][j][i][d]
__device__ float g_pred[(size_t)BS * J * NPIX * D2];           // 134 MB scratch
__device__ float g_L[(size_t)BS * J * NPIX];                   // 4 MB logits (after iter-1 update)
__device__ float g_spart[(size_t)BS * NCH * J * D2];           // 8 MB partial s (deterministic, no atomics)
__device__ float g_v[(size_t)BS * J * D2];                     // 512 KB v between iterations

// ---------------------------------------------------------------------------
// Packed fp32x2 FMA helpers (Blackwell sm_103a)
// ---------------------------------------------------------------------------
#define FFMA2(acc, aa, bb) \
    asm("fma.rn.f32x2 %0, %1, %2, %0;" : "+l"(acc) : "l"(aa), "l"(bb))
#define DUP2(dst, s) \
    asm("mov.b64 %0, {%1, %1};" : "=l"(dst) : "r"(s))

// ---------------------------------------------------------------------------
// Kernel 1: SGEMM with f32x2 packed FMA.
// pred[b][j][i][d] = sum_ic W[(j*32+d)*256+ic] * x[b][ic][i] + Wb
// Tile: 128(o) x 128(i), BK=16, 256 threads, 8x8 microtile (packed along i).
// ---------------------------------------------------------------------------
#define BM 128
#define BN 128
#define BK 16

__global__ __launch_bounds__(256) void gemm_kernel(
    const float* __restrict__ W,
    const float* __restrict__ x,
    const float* __restrict__ Wb)
{
    __shared__ float As[BK][BM];          // A transposed: As[k][o_local]
    __shared__ float Bs[BK][BN];          // Bs[k][i_local]
    __shared__ float Cs[32][BN + 1];      // 32-o-row staging chunk

    const int b  = blockIdx.z;
    const int o0 = blockIdx.x * BM;
    const int i0 = blockIdx.y * BN;
    const int tid = threadIdx.x;
    const int ty8 = tid >> 4;             // 0..15
    const int tx8 = tid & 15;             // 0..15
    const int r0 = ty8 * 8;
    const int c0 = tx8 * 8;

    const float* xb = x + (size_t)b * IC * NPIX;

    unsigned long long acc2[8][4];
    #pragma unroll
    for (int r = 0; r < 8; r++)
        #pragma unroll
        for (int c = 0; c < 4; c++) acc2[r][c] = 0ull;

    for (int k0 = 0; k0 < IC; k0 += BK) {
        // A tile: W[o0+r][k0+k4..k4+3], 2 rows per thread
        {
            int r  = tid >> 2;
            int k4 = (tid & 3) * 4;
            #pragma unroll
            for (int h = 0; h < 2; h++) {
                int rr = r + h * 64;
                float4 a = *reinterpret_cast<const float4*>(
                    W + (size_t)(o0 + rr) * IC + k0 + k4);
                As[k4 + 0][rr] = a.x;
                As[k4 + 1][rr] = a.y;
                As[k4 + 2][rr] = a.z;
                As[k4 + 3][rr] = a.w;
            }
        }
        // B tile: x[b][k0+kr][i0+col], float4 coalesced
        {
            int col4 = (tid & 31) * 4;
            int kr   = tid >> 5;
            #pragma unroll
            for (int h = 0; h < 2; h++) {
                int kk = kr + h * 8;
                *reinterpret_cast<float4*>(&Bs[kk][col4]) =
                    *reinterpret_cast<const float4*>(xb + (size_t)(k0 + kk) * NPIX + i0 + col4);
            }
        }
        __syncthreads();

        #pragma unroll
        for (int k = 0; k < BK; k++) {
            const ulonglong2* bq = reinterpret_cast<const ulonglong2*>(&Bs[k][c0]);
            ulonglong2 b01 = bq[0];       // pairs (c0,c0+1),(c0+2,c0+3)
            ulonglong2 b23 = bq[1];       // pairs (c0+4,c0+5),(c0+6,c0+7)
            const float4* af = reinterpret_cast<const float4*>(&As[k][r0]);
            float4 a0 = af[0], a1 = af[1];
            float ar[8] = {a0.x, a0.y, a0.z, a0.w, a1.x, a1.y, a1.z, a1.w};
            #pragma unroll
            for (int r = 0; r < 8; r++) {
                unsigned long long ad;
                DUP2(ad, __float_as_uint(ar[r]));
                FFMA2(acc2[r][0], ad, b01.x);
                FFMA2(acc2[r][1], ad, b01.y);
                FFMA2(acc2[r][2], ad, b23.x);
                FFMA2(acc2[r][3], ad, b23.y);
            }
        }
        __syncthreads();
    }

    // Epilogue: 4 chunks of 32 o-rows, staged through Cs for coalesced writes.
    const int jbase = o0 >> 5;            // j index base (o0/32)
    #pragma unroll
    for (int ch = 0; ch < 4; ch++) {
        __syncthreads();
        if ((ty8 >> 2) == ch) {
            int ob = (ty8 & 3) * 8;       // o_l base for this thread
            #pragma unroll
            for (int r = 0; r < 8; r++) {
                int o_l = ob + r;
                float bias = Wb[o0 + ch * 32 + o_l];
                #pragma unroll
                for (int cp = 0; cp < 4; cp++) {
                    unsigned long long v = acc2[r][cp];
                    float lo = __uint_as_float((unsigned)(v & 0xffffffffull));
                    float hi = __uint_as_float((unsigned)(v >> 32));
                    Cs[o_l][c0 + 2 * cp + 0] = lo + bias;
                    Cs[o_l][c0 + 2 * cp + 1] = hi + bias;
                }
            }
        }
        __syncthreads();
        // write out: per i, 32 contiguous d (=o_l). Conflict-free (stride 129).
        for (int e = tid; e < 32 * BN; e += 256) {
            int i_l = e >> 5;
            int o_l = e & 31;
            size_t dst = (((size_t)b * J + jbase + ch) * NPIX + (i0 + i_l)) * D2 + o_l;
            g_pred[dst] = Cs[o_l][i_l];
        }
    }
}

// ---------------------------------------------------------------------------
// Kernel 2: fused routing sweep. One CTA per (b, i-chunk of 16 pixels).
// it==0:           c = softmax(b_init); partial s
// it==1: db from v0; L = b_init + db (write g_L); c = softmax(L); partial s
// it==2: db from v1; L = g_L + db (no write);     c = softmax(L); partial s
// ---------------------------------------------------------------------------
#define LCP 17   // padded row stride for Lc (conflict-free column access)

__global__ __launch_bounds__(512) void route_kernel(
    const float* __restrict__ b_init, int it)
{
    __shared__ float Lc[J * LCP];         // logits chunk [j][ii], padded
    __shared__ float vbuf[J * D2];        // v from previous squash
    __shared__ float mx[CHI], rd[CHI];    // softmax stats per pixel

    const int ch  = blockIdx.x;
    const int b   = blockIdx.y;
    const int i0  = ch * CHI;
    const int tid = threadIdx.x;
    const int w   = tid >> 5;             // 0..15
    const int lane = tid & 31;

    const float* Lsrc = (it == 2) ? g_L : b_init;

    // load logits chunk
    for (int e = tid; e < J * CHI; e += 512) {
        int j = e >> 4, ii = e & 15;
        Lc[j * LCP + ii] = Lsrc[((size_t)b * J + j) * NPIX + i0 + ii];
    }
    if (it) {
        for (int e = tid; e < J * D2; e += 512)
            vbuf[e] = g_v[(size_t)b * J * D2 + e];
    }
    __syncthreads();

    // ---- Phase D: db[j,i] = v_j . P[j,i,:], update Lc (and g_L on it==1) ----
    if (it) {
        int i_l = lane & 15, h = lane >> 4;   // 2 lanes per pixel, each 16 d's
        #pragma unroll
        for (int jj = 0; jj < 4; jj++) {
            int j = w * 4 + jj;
            const float4* p4 = reinterpret_cast<const float4*>(
                g_pred + (((size_t)b * J + j) * NPIX + i0 + i_l) * D2 + h * 16);
            const float4* v4 = reinterpret_cast<const float4*>(vbuf + j * D2 + h * 16);
            float acc = 0.f;
            #pragma unroll
            for (int u = 0; u < 4; u++) {
                float4 p = p4[u], v = v4[u];
                acc += p.x * v.x + p.y * v.y + p.z * v.z + p.w * v.w;
            }
            acc += __shfl_xor_sync(0xFFFFFFFFu, acc, 16);
            if (h == 0) {
                float nl = Lc[j * LCP + i_l] + acc;
                Lc[j * LCP + i_l] = nl;
                if (it == 1)
                    g_L[((size_t)b * J + j) * NPIX + i0 + i_l] = nl;
            }
        }
        __syncthreads();
    }

    // ---- Softmax stats over J per pixel: warp w owns pixel i_l = w ----
    {
        float v0 = Lc[lane * LCP + w];
        float v1 = Lc[(lane + 32) * LCP + w];
        float m = fmaxf(v0, v1);
        #pragma unroll
        for (int o = 16; o; o >>= 1) m = fmaxf(m, __shfl_xor_sync(0xFFFFFFFFu, m, o));
        float sum = __expf(v0 - m) + __expf(v1 - m);
        #pragma unroll
        for (int o = 16; o; o >>= 1) sum += __shfl_xor_sync(0xFFFFFFFFu, sum, o);
        if (lane == 0) { mx[w] = m; rd[w] = 1.0f / sum; }
    }
    __syncthreads();

    // ---- Phase B: partial s[j][d] over this chunk's 16 pixels ----
    #pragma unroll
    for (int jj = 0; jj < 4; jj++) {
        int j = w * 4 + jj;
        const float* Pj = g_pred + (((size_t)b * J + j) * NPIX + i0) * D2;
        const float* Lj = Lc + j * LCP;
        float acc = 0.f;
        #pragma unroll
        for (int ii = 0; ii < CHI; ii++) {
            float c = __expf(Lj[ii] - mx[ii]) * rd[ii];
            acc = fmaf(c, Pj[ii * D2 + lane], acc);
        }
        g_spart[(((size_t)b * NCH + ch) * J + j) * D2 + lane] = acc;
    }
}

// ---------------------------------------------------------------------------
// Kernel 3: sum partials + squash. One warp per (b, j).
// ---------------------------------------------------------------------------
__global__ __launch_bounds__(256) void squash_kernel(float* __restrict__ out, int final_it)
{
    int gw   = blockIdx.x * 8 + (threadIdx.x >> 5);   // 0..4095
    int b    = gw >> 6;
    int j    = gw & 63;
    int lane = threadIdx.x & 31;

    float s = 0.f;
    const float* base = g_spart + (((size_t)b * NCH) * J + j) * D2 + lane;
    #pragma unroll
    for (int ch = 0; ch < NCH; ch++)
        s += base[(size_t)ch * J * D2];

    float sq = s * s;
    #pragma unroll
    for (int o = 16; o; o >>= 1) sq += __shfl_xor_sync(0xFFFFFFFFu, sq, o);
    float scale = (sq / (1.0f + sq)) * rsqrtf(sq + 1e-8f);
    float v = scale * s;

    if (final_it) out[((size_t)b * J + j) * D2 + lane] = v;
    else          g_v[((size_t)b * J + j) * D2 + lane] = v;
}

// ---------------------------------------------------------------------------
// Launch: gemm, then 3x (route, squash). 7 launches, all graph-capturable.
// Inputs: x[64,256,16,16] f32, b_init[64,64,256] f32, W[2048,256] f32, Wb[2048] f32
// Output: v[64,64,32] f32
// ---------------------------------------------------------------------------
extern "C" void kernel_launch(void* const* d_in, const int* in_sizes, int n_in,
                              void* d_out, int out_size)
{
    const float* x      = (const float*)d_in[0];
    const float* b_init = (const float*)d_in[1];
    const float* W      = (const float*)d_in[2];
    const float* Wb     = (const float*)d_in[3];
    float* out = (float*)d_out;

    dim3 ggrid(OUT / BM, NPIX / BN, BS);          // 16 x 2 x 64
    gemm_kernel<<<ggrid, 256>>>(W, x, Wb);

    dim3 rgrid(NCH, BS);                          // 16 x 64 = 1024 CTAs
    route_kernel<<<rgrid, 512>>>(b_init, 0);
    squash_kernel<<<512, 256>>>(out, 0);
    route_kernel<<<rgrid, 512>>>(b_init, 1);
    squash_kernel<<<512, 256>>>(out, 0);
    route_kernel<<<rgrid, 512>>>(b_init, 2);
    squash_kernel<<<512, 256>>>(out, 1);
}

// round 7
// speedup vs baseline: 2.2856x; 1.5631x over previous
#include <cuda_runtime.h>
#include <cuda_bf16.h>
#include <cstdint>

// Problem constants
#define BS   64
#define IC   256     // in_dim (GEMM K)
#define NPIX 256     // 16*16 pixels
#define J    64      // out caps
#define D2   32      // dim per cap
#define OUT  2048    // J*D2

#define NCH  16      // routing i-chunks
#define CHI  16      // pixels per chunk

// pred layout: [b][j][i][d]
__device__ float g_pred[(size_t)BS * J * NPIX * D2];      // 134 MB
__device__ float g_L[(size_t)BS * J * NPIX];              // logits after iter-1
__device__ float g_spart[(size_t)BS * NCH * J * D2];      // partial s
__device__ float g_v[(size_t)BS * J * D2];                // v between iters

// bf16 hi/lo split operands
__device__ __nv_bfloat16 g_Wh[(size_t)OUT * IC];
__device__ __nv_bfloat16 g_Wl[(size_t)OUT * IC];
__device__ __nv_bfloat16 g_Xh[(size_t)BS * NPIX * IC];    // [b][i][ic] (K-major)
__device__ __nv_bfloat16 g_Xl[(size_t)BS * NPIX * IC];

// ---------------------------------------------------------------------------
// Helpers (baseline PTX only — valid on compute_103)
// ---------------------------------------------------------------------------
__device__ __forceinline__ uint32_t smem_u32(const void* p) {
    uint32_t a;
    asm("{ .reg .u64 t; cvta.to.shared.u64 t, %1; cvt.u32.u64 %0, t; }"
        : "=r"(a) : "l"(p));
    return a;
}
__device__ __forceinline__ void ldsm4(uint32_t& r0, uint32_t& r1,
                                      uint32_t& r2, uint32_t& r3, uint32_t addr) {
    asm volatile("ldmatrix.sync.aligned.m8n8.x4.shared.b16 {%0,%1,%2,%3}, [%4];"
                 : "=r"(r0), "=r"(r1), "=r"(r2), "=r"(r3) : "r"(addr));
}
__device__ __forceinline__ void mma_bf16(float* c, const uint32_t* a,
                                         uint32_t b0, uint32_t b1) {
    asm volatile(
        "mma.sync.aligned.m16n8k16.row.col.f32.bf16.bf16.f32 "
        "{%0,%1,%2,%3}, {%4,%5,%6,%7}, {%8,%9}, {%0,%1,%2,%3};"
        : "+f"(c[0]), "+f"(c[1]), "+f"(c[2]), "+f"(c[3])
        : "r"(a[0]), "r"(a[1]), "r"(a[2]), "r"(a[3]), "r"(b0), "r"(b1));
}

#define SWZ(o) ((o) ^ (((o) >> 3) & 0x70))

// ---------------------------------------------------------------------------
// Conversion kernels: fp32 -> bf16 hi/lo split
// ---------------------------------------------------------------------------
__global__ __launch_bounds__(256) void conv_w(const float* __restrict__ W) {
    int i = blockIdx.x * 256 + threadIdx.x;
    float v = W[i];
    __nv_bfloat16 h = __float2bfloat16(v);
    g_Wh[i] = h;
    g_Wl[i] = __float2bfloat16(v - __bfloat162float(h));
}

__global__ __launch_bounds__(256) void conv_x(const float* __restrict__ x) {
    __shared__ float t[32][33];
    int b   = blockIdx.z;
    int i0  = blockIdx.x * 32;
    int ic0 = blockIdx.y * 32;
    int tx = threadIdx.x, ty = threadIdx.y;   // 32 x 8
    #pragma unroll
    for (int q = 0; q < 4; q++)
        t[ty + q * 8][tx] = x[((size_t)b * IC + ic0 + ty + q * 8) * NPIX + i0 + tx];
    __syncthreads();
    #pragma unroll
    for (int q = 0; q < 4; q++) {
        float v = t[tx][ty + q * 8];
        __nv_bfloat16 h = __float2bfloat16(v);
        size_t o = ((size_t)b * NPIX + i0 + ty + q * 8) * IC + ic0 + tx;
        g_Xh[o] = h;
        g_Xl[o] = __float2bfloat16(v - __bfloat162float(h));
    }
}

// ---------------------------------------------------------------------------
// GEMM via mma.sync bf16 hi/lo split.
// Per CTA: M=128(o) x N=128(i), K=256 in 4 chunks of 64.
// 8 warps: warp_m = wid>>2 (2), warp_n = wid&3 (4); warp tile 64x32.
// smem per chunk: Ah|Al|Bh|Bl, each 128 rows x 128B (SW128 swizzled) = 64 KB.
// ---------------------------------------------------------------------------
#define GSMEM 65536

__global__ __launch_bounds__(256, 1) void gemm_mma(const float* __restrict__ Wbias) {
    extern __shared__ char smem[];
    const uint32_t sb = smem_u32(smem);

    const int b    = blockIdx.z;
    const int o0   = blockIdx.x * 128;
    const int i0   = blockIdx.y * 128;
    const int tid  = threadIdx.x;
    const int wid  = tid >> 5;
    const int lane = tid & 31;
    const int wm   = wid >> 2;           // 0..1  (M)
    const int wn   = wid & 3;            // 0..3  (N)

    const __nv_bfloat16* xh = g_Xh + (size_t)b * NPIX * IC;
    const __nv_bfloat16* xl = g_Xl + (size_t)b * NPIX * IC;

    float acc[4][4][4];                  // [mt][nt][e]
    #pragma unroll
    for (int mt = 0; mt < 4; mt++)
        #pragma unroll
        for (int nt = 0; nt < 4; nt++)
            #pragma unroll
            for (int e = 0; e < 4; e++) acc[mt][nt][e] = 0.f;

    // per-thread ldmatrix row addressing: row = lane&15, half = lane>>4
    const int lrow = lane & 15;
    const uint32_t lhalf = (uint32_t)(lane >> 4) * 16;

    for (int c = 0; c < 4; c++) {
        // ---- cooperative load of Ah|Al|Bh|Bl (swizzled) ----
        #pragma unroll
        for (int q = 0; q < 4; q++) {
            int idx = tid + q * 256;              // 0..1023
            int row = idx >> 3, seg = idx & 7;
            uint32_t sw = SWZ((uint32_t)(row * 128 + seg * 16));
            size_t wsrc = (size_t)(o0 + row) * IC + c * 64 + seg * 8;
            size_t xsrc = (size_t)(i0 + row) * IC + c * 64 + seg * 8;
            *(uint4*)(smem +          sw) = *(const uint4*)(g_Wh + wsrc);
            *(uint4*)(smem + 16384u + sw) = *(const uint4*)(g_Wl + wsrc);
            *(uint4*)(smem + 32768u + sw) = *(const uint4*)(xh + xsrc);
            *(uint4*)(smem + 49152u + sw) = *(const uint4*)(xl + xsrc);
        }
        __syncthreads();

        #pragma unroll
        for (int ks = 0; ks < 4; ks++) {
            const uint32_t koff = lhalf + (uint32_t)ks * 32;

            // B frags: 2 x ldmatrix.x4 per version (covers nt pairs)
            uint32_t bh[4][2], bl[4][2];
            #pragma unroll
            for (int p = 0; p < 2; p++) {
                int brow = wn * 32 + p * 16 + lrow;
                uint32_t off = SWZ((uint32_t)(brow * 128) + koff);
                uint32_t r0, r1, r2, r3;
                ldsm4(r0, r1, r2, r3, sb + 32768u + off);
                bh[p * 2 + 0][0] = r0; bh[p * 2 + 0][1] = r2;
                bh[p * 2 + 1][0] = r1; bh[p * 2 + 1][1] = r3;
                ldsm4(r0, r1, r2, r3, sb + 49152u + off);
                bl[p * 2 + 0][0] = r0; bl[p * 2 + 0][1] = r2;
                bl[p * 2 + 1][0] = r1; bl[p * 2 + 1][1] = r3;
            }

            // A frags + MMAs per mt
            #pragma unroll
            for (int mt = 0; mt < 4; mt++) {
                int arow = wm * 64 + mt * 16 + lrow;
                uint32_t off = SWZ((uint32_t)(arow * 128) + koff);
                uint32_t ah[4], al[4];
                ldsm4(ah[0], ah[1], ah[2], ah[3], sb + off);
                ldsm4(al[0], al[1], al[2], al[3], sb + 16384u + off);
                #pragma unroll
                for (int nt = 0; nt < 4; nt++) {
                    mma_bf16(acc[mt][nt], ah, bh[nt][0], bh[nt][1]);
                    mma_bf16(acc[mt][nt], ah, bl[nt][0], bl[nt][1]);
                    mma_bf16(acc[mt][nt], al, bh[nt][0], bh[nt][1]);
                }
            }
        }
        __syncthreads();
    }

    // ---- Epilogue: 4 chunks of 32 o-rows, staged via smem ----
    float (*Cs)[129] = reinterpret_cast<float (*)[129]>(smem);   // 32 x 129
    #pragma unroll
    for (int ch = 0; ch < 4; ch++) {
        if (wm == (ch >> 1)) {
            #pragma unroll
            for (int ml = 0; ml < 2; ml++) {
                int mt = (ch & 1) * 2 + ml;
                #pragma unroll
                for (int nt = 0; nt < 4; nt++) {
                    #pragma unroll
                    for (int e = 0; e < 4; e++) {
                        int o_l = ml * 16 + (lane >> 2) + (e >> 1) * 8;
                        int i_l = wn * 32 + nt * 8 + (lane & 3) * 2 + (e & 1);
                        Cs[o_l][i_l] = acc[mt][nt][e];
                    }
                }
            }
        }
        __syncthreads();
        // coalesced write-out: per i, 32 contiguous d
        int jg = (o0 >> 5) + ch;
        for (int e = tid; e < 32 * 128; e += 256) {
            int i_l = e >> 5;
            int o_l = e & 31;
            size_t dst = (((size_t)b * J + jg) * NPIX + (i0 + i_l)) * D2 + o_l;
            g_pred[dst] = Cs[o_l][i_l] + Wbias[o0 + ch * 32 + o_l];
        }
        __syncthreads();
    }
}

// ---------------------------------------------------------------------------
// Routing sweep: one CTA per (b, i-chunk of 16 pixels).
// ---------------------------------------------------------------------------
#define LCP 17

__global__ __launch_bounds__(512) void route_kernel(
    const float* __restrict__ b_init, int it)
{
    __shared__ float Lc[J * LCP];
    __shared__ float vbuf[J * D2];
    __shared__ float cbuf[J * CHI];
    __shared__ float mx[CHI], rd[CHI];

    const int ch  = blockIdx.x;
    const int b   = blockIdx.y;
    const int i0  = ch * CHI;
    const int tid = threadIdx.x;
    const int w   = tid >> 5;
    const int lane = tid & 31;

    const float* Lsrc = (it == 2) ? g_L : b_init;

    for (int e = tid; e < J * CHI; e += 512) {
        int j = e >> 4, ii = e & 15;
        Lc[j * LCP + ii] = Lsrc[((size_t)b * J + j) * NPIX + i0 + ii];
    }
    if (it) {
        for (int e = tid; e < J * D2; e += 512)
            vbuf[e] = g_v[(size_t)b * J * D2 + e];
    }
    __syncthreads();

    // Phase D: db[j,i] = v_j . P[j,i,:]
    if (it) {
        int i_l = lane & 15, h = lane >> 4;
        #pragma unroll
        for (int jj = 0; jj < 4; jj++) {
            int j = w * 4 + jj;
            const float4* p4 = reinterpret_cast<const float4*>(
                g_pred + (((size_t)b * J + j) * NPIX + i0 + i_l) * D2 + h * 16);
            const float4* v4 = reinterpret_cast<const float4*>(vbuf + j * D2 + h * 16);
            float acc = 0.f;
            #pragma unroll
            for (int u = 0; u < 4; u++) {
                float4 p = p4[u], v = v4[u];
                acc += p.x * v.x + p.y * v.y + p.z * v.z + p.w * v.w;
            }
            acc += __shfl_xor_sync(0xFFFFFFFFu, acc, 16);
            if (h == 0) {
                float nl = Lc[j * LCP + i_l] + acc;
                Lc[j * LCP + i_l] = nl;
                if (it == 1)
                    g_L[((size_t)b * J + j) * NPIX + i0 + i_l] = nl;
            }
        }
        __syncthreads();
    }

    // Softmax stats over J per pixel (warp w owns pixel w)
    {
        float v0 = Lc[lane * LCP + w];
        float v1 = Lc[(lane + 32) * LCP + w];
        float m = fmaxf(v0, v1);
        #pragma unroll
        for (int o = 16; o; o >>= 1) m = fmaxf(m, __shfl_xor_sync(0xFFFFFFFFu, m, o));
        float sum = __expf(v0 - m) + __expf(v1 - m);
        #pragma unroll
        for (int o = 16; o; o >>= 1) sum += __shfl_xor_sync(0xFFFFFFFFu, sum, o);
        if (lane == 0) { mx[w] = m; rd[w] = 1.0f / sum; }
    }
    __syncthreads();

    for (int e = tid; e < J * CHI; e += 512) {
        int j = e >> 4, ii = e & 15;
        cbuf[e] = __expf(Lc[j * LCP + ii] - mx[ii]) * rd[ii];
    }
    __syncthreads();

    // Phase B: partial s[j][d]
    #pragma unroll
    for (int jj = 0; jj < 4; jj++) {
        int j = w * 4 + jj;
        const float* Pj = g_pred + (((size_t)b * J + j) * NPIX + i0) * D2;
        const float* Cj = cbuf + j * CHI;
        float acc = 0.f;
        #pragma unroll
        for (int ii = 0; ii < CHI; ii++)
            acc = fmaf(Cj[ii], Pj[ii * D2 + lane], acc);
        g_spart[(((size_t)b * NCH + ch) * J + j) * D2 + lane] = acc;
    }
}

// ---------------------------------------------------------------------------
// Sum partials + squash. One warp per (b, j).
// ---------------------------------------------------------------------------
__global__ __launch_bounds__(256) void squash_kernel(float* __restrict__ out, int final_it)
{
    int gw   = blockIdx.x * 8 + (threadIdx.x >> 5);
    int b    = gw >> 6;
    int j    = gw & 63;
    int lane = threadIdx.x & 31;

    float s = 0.f;
    const float* base = g_spart + (((size_t)b * NCH) * J + j) * D2 + lane;
    #pragma unroll
    for (int ch = 0; ch < NCH; ch++)
        s += base[(size_t)ch * J * D2];

    float sq = s * s;
    #pragma unroll
    for (int o = 16; o; o >>= 1) sq += __shfl_xor_sync(0xFFFFFFFFu, sq, o);
    float scale = (sq / (1.0f + sq)) * rsqrtf(sq + 1e-8f);
    float v = scale * s;

    if (final_it) out[((size_t)b * J + j) * D2 + lane] = v;
    else          g_v[((size_t)b * J + j) * D2 + lane] = v;
}

// ---------------------------------------------------------------------------
// Launch
// Inputs: x[64,256,16,16] f32, b_init[64,64,256] f32, W[2048,256] f32, Wb[2048] f32
// ---------------------------------------------------------------------------
extern "C" void kernel_launch(void* const* d_in, const int* in_sizes, int n_in,
                              void* d_out, int out_size)
{
    const float* x      = (const float*)d_in[0];
    const float* b_init = (const float*)d_in[1];
    const float* W      = (const float*)d_in[2];
    const float* Wb     = (const float*)d_in[3];
    float* out = (float*)d_out;

    conv_w<<<(OUT * IC) / 256, 256>>>(W);
    conv_x<<<dim3(8, 8, BS), dim3(32, 8)>>>(x);

    cudaFuncSetAttribute(gemm_mma, cudaFuncAttributeMaxDynamicSharedMemorySize, GSMEM);
    dim3 ggrid(OUT / 128, NPIX / 128, BS);        // 16 x 2 x 64
    gemm_mma<<<ggrid, 256, GSMEM>>>(Wb);

    dim3 rgrid(NCH, BS);
    route_kernel<<<rgrid, 512>>>(b_init, 0);
    squash_kernel<<<512, 256>>>(out, 0);
    route_kernel<<<rgrid, 512>>>(b_init, 1);
    squash_kernel<<<512, 256>>>(out, 0);
    route_kernel<<<rgrid, 512>>>(b_init, 2);
    squash_kernel<<<512, 256>>>(out, 1);
}